// round 7
// baseline (speedup 1.0000x reference)
#include <cuda_runtime.h>
#include <cuda_fp16.h>
#include <math.h>
#include <cstdint>

// Problem constants: B=4, S=2048, Hd=1024, H=8, dk=128, wA=67
#define NBH   32           // B*H
#define SEQ   2048
#define DKD   128
#define WAW   67
#define OUT1_ELEMS (4*2048*536)   // B*S*(H*wA)

// ---------------- scratch (static device globals; no allocation) ----------------
__device__ float g_Q[NBH*SEQ*DKD];   // (b,h,s,d), pre-scaled by dk^-0.5
__device__ float g_K[NBH*SEQ*DKD];
__device__ float g_cD[NBH*SEQ*WAW];  // (b,h,s,w)

__constant__ float c_lo[8] = { -0.010597401784997278f, 0.032883011666982945f,
                                0.030841381835986965f, -0.18703481171888114f,
                               -0.02798376941698385f,  0.6308807679295904f,
                                0.7148465705525415f,   0.23037781330885523f };
__constant__ float c_hi[8] = { -0.23037781330885523f,  0.7148465705525415f,
                               -0.6308807679295904f,  -0.02798376941698385f,
                                0.18703481171888114f,  0.030841381835986965f,
                               -0.032883011666982945f, -0.010597401784997278f };

__device__ __forceinline__ uint32_t f2tf32(float f) {
    uint32_t u;
    asm("cvt.rna.tf32.f32 %0, %1;" : "=r"(u) : "f"(f));
    return u;
}

__device__ __forceinline__ void mma_tf32(float& d0, float& d1, float& d2, float& d3,
                                         uint32_t a0, uint32_t a1, uint32_t a2, uint32_t a3,
                                         uint32_t b0, uint32_t b1) {
    asm volatile(
        "mma.sync.aligned.m16n8k8.row.col.f32.tf32.tf32.f32 "
        "{%0,%1,%2,%3}, {%4,%5,%6,%7}, {%8,%9}, {%0,%1,%2,%3};"
        : "+f"(d0), "+f"(d1), "+f"(d2), "+f"(d3)
        : "r"(a0), "r"(a1), "r"(a2), "r"(a3), "r"(b0), "r"(b1));
}

__device__ __forceinline__ void mma_f16(float& d0, float& d1, float& d2, float& d3,
                                        uint32_t a0, uint32_t a1, uint32_t a2, uint32_t a3,
                                        uint32_t b0, uint32_t b1) {
    asm volatile(
        "mma.sync.aligned.m16n8k16.row.col.f32.f16.f16.f32 "
        "{%0,%1,%2,%3}, {%4,%5,%6,%7}, {%8,%9}, {%0,%1,%2,%3};"
        : "+f"(d0), "+f"(d1), "+f"(d2), "+f"(d3)
        : "r"(a0), "r"(a1), "r"(a2), "r"(a3), "r"(b0), "r"(b1));
}

// split fp32 pair -> fp16 hi pair + fp16 lo (residual) pair, packed as b32
__device__ __forceinline__ void split_h2(float x, float y, uint32_t& hi, uint32_t& lo) {
    __half2 h = __float22half2_rn(make_float2(x, y));
    float2 b = __half22float2(h);
    __half2 l = __float22half2_rn(make_float2(x - b.x, y - b.y));
    hi = *(uint32_t*)&h;
    lo = *(uint32_t*)&l;
}

// ======================================================================
// Kernel 1: QKV projection via mma.sync tf32; V-epilogue fuses db4 DWT.
// (unchanged from R6 pass)
// ======================================================================
#define CHN 4608            // 128*36 floats per buffer
#define QKV_SMEM (4*CHN*4)  // As[2] + Bs[2] = 73728 bytes

__global__ __launch_bounds__(256, 2) void qkv_mma_kernel(
    const float* __restrict__ x, const float* __restrict__ Wq,
    const float* __restrict__ Wk, const float* __restrict__ Wv,
    float* __restrict__ out2)
{
    extern __shared__ float sm[];
    float* As = sm;             // [2][128][36]
    float* Bs = sm + 2*CHN;     // [2][128][36]

    const int tid  = threadIdx.x;
    const int lane = tid & 31;
    const int warp = tid >> 5;
    const int g    = lane >> 2;
    const int tig  = lane & 3;
    const int wm   = warp & 3;
    const int wn   = warp >> 2;

    const int which = blockIdx.z;
    const float* W = (which == 0) ? Wq : ((which == 1) ? Wk : Wv);
    const float scale = (which == 0) ? 0.08838834764831845f : 1.0f;

    const int m0   = blockIdx.y * 128;
    const int head = blockIdx.x;
    const float* xb = x + (size_t)m0 * 1024;
    const float* wb = W + (size_t)head * 128 * 1024;

    const int lr = tid >> 3;
    const int lc = (tid & 7) * 4;

    float c[2][8][4];
#pragma unroll
    for (int mt = 0; mt < 2; mt++)
#pragma unroll
        for (int nt = 0; nt < 8; nt++)
#pragma unroll
            for (int q = 0; q < 4; q++) c[mt][nt][q] = 0.0f;

    {
#pragma unroll
        for (int u = 0; u < 4; u++) {
            const int r = lr + 32*u;
            const float4 a4 = *(const float4*)(xb + (size_t)r*1024 + lc);
            const float4 b4 = *(const float4*)(wb + (size_t)r*1024 + lc);
            float* pa = As + r*36 + lc;
            float* pb = Bs + r*36 + lc;
            pa[0] = __uint_as_float(f2tf32(a4.x)); pa[1] = __uint_as_float(f2tf32(a4.y));
            pa[2] = __uint_as_float(f2tf32(a4.z)); pa[3] = __uint_as_float(f2tf32(a4.w));
            pb[0] = __uint_as_float(f2tf32(b4.x)); pb[1] = __uint_as_float(f2tf32(b4.y));
            pb[2] = __uint_as_float(f2tf32(b4.z)); pb[3] = __uint_as_float(f2tf32(b4.w));
        }
    }
    __syncthreads();

    for (int ch = 0; ch < 32; ch++) {
        const int cur = ch & 1;
        float4 pfa[4], pfb[4];
        if (ch < 31) {
            const int kb = (ch + 1) << 5;
#pragma unroll
            for (int u = 0; u < 4; u++) {
                const int r = lr + 32*u;
                pfa[u] = *(const float4*)(xb + (size_t)r*1024 + kb + lc);
                pfb[u] = *(const float4*)(wb + (size_t)r*1024 + kb + lc);
            }
        }

        const float* as = As + cur*CHN;
        const float* bs = Bs + cur*CHN;
#pragma unroll
        for (int ks = 0; ks < 4; ks++) {
            const int k0 = ks * 8;
            uint32_t a[2][4];
#pragma unroll
            for (int mt = 0; mt < 2; mt++) {
                const int rb = wm*32 + mt*16 + g;
                a[mt][0] = __float_as_uint(as[(rb    )*36 + k0 + tig]);
                a[mt][1] = __float_as_uint(as[(rb + 8)*36 + k0 + tig]);
                a[mt][2] = __float_as_uint(as[(rb    )*36 + k0 + tig + 4]);
                a[mt][3] = __float_as_uint(as[(rb + 8)*36 + k0 + tig + 4]);
            }
#pragma unroll
            for (int nt = 0; nt < 8; nt++) {
                const int nb = wn*64 + nt*8 + g;
                const uint32_t b0 = __float_as_uint(bs[nb*36 + k0 + tig]);
                const uint32_t b1 = __float_as_uint(bs[nb*36 + k0 + tig + 4]);
#pragma unroll
                for (int mt = 0; mt < 2; mt++)
                    mma_tf32(c[mt][nt][0], c[mt][nt][1], c[mt][nt][2], c[mt][nt][3],
                             a[mt][0], a[mt][1], a[mt][2], a[mt][3], b0, b1);
            }
        }

        if (ch < 31) {
            float* pa0 = As + (cur^1)*CHN;
            float* pb0 = Bs + (cur^1)*CHN;
#pragma unroll
            for (int u = 0; u < 4; u++) {
                const int r = lr + 32*u;
                float* pa = pa0 + r*36 + lc;
                float* pb = pb0 + r*36 + lc;
                pa[0] = __uint_as_float(f2tf32(pfa[u].x)); pa[1] = __uint_as_float(f2tf32(pfa[u].y));
                pa[2] = __uint_as_float(f2tf32(pfa[u].z)); pa[3] = __uint_as_float(f2tf32(pfa[u].w));
                pb[0] = __uint_as_float(f2tf32(pfb[u].x)); pb[1] = __uint_as_float(f2tf32(pfb[u].y));
                pb[2] = __uint_as_float(f2tf32(pfb[u].z)); pb[3] = __uint_as_float(f2tf32(pfb[u].w));
            }
        }
        __syncthreads();
    }

    if (which < 2) {
        float* O = (which == 0) ? g_Q : g_K;
#pragma unroll
        for (int mt = 0; mt < 2; mt++) {
            const int m  = m0 + wm*32 + mt*16 + g;
            const int b0_ = m >> 11, sq = m & 2047;
            float* dst0 = O + (((size_t)(b0_*8 + head) * 2048 + sq) << 7);
            float* dst1 = dst0 + (8 << 7);
#pragma unroll
            for (int nt = 0; nt < 8; nt++) {
                const int d = wn*64 + nt*8 + 2*tig;
                float2 v0 = make_float2(c[mt][nt][0]*scale, c[mt][nt][1]*scale);
                float2 v1 = make_float2(c[mt][nt][2]*scale, c[mt][nt][3]*scale);
                *(float2*)(dst0 + d) = v0;
                *(float2*)(dst1 + d) = v1;
            }
        }
    } else {
        // ---- V epilogue: stage tile in SMEM, fused db4 DWT ----
        float* Vt = sm;           // [128][132]
#pragma unroll
        for (int mt = 0; mt < 2; mt++) {
            const int r0 = wm*32 + mt*16 + g;
#pragma unroll
            for (int nt = 0; nt < 8; nt++) {
                const int d = wn*64 + nt*8 + 2*tig;
                *(float2*)(Vt + (r0    )*132 + d) = make_float2(c[mt][nt][0], c[mt][nt][1]);
                *(float2*)(Vt + (r0 + 8)*132 + d) = make_float2(c[mt][nt][2], c[mt][nt][3]);
            }
        }
        __syncthreads();
        const int r    = tid >> 1;
        const int half = tid & 1;
        const int m    = m0 + r;
        const int b0_  = m >> 11, sq = m & 2047;
        const size_t rowbase = ((size_t)(b0_*8 + head) * 2048 + sq) * WAW;
        const float* v = Vt + r*132;
        for (int t = half; t < WAW; t += 2) {
            float a = 0.0f, d = 0.0f;
#pragma unroll
            for (int k = 0; k < 8; k++) {
                const int j = 2*t + k;
                const int src = (j < 6) ? (5 - j) : ((j < 134) ? (j - 6) : (261 - j));
                const float e = v[src];
                a = fmaf(e, c_lo[7 - k], a);
                d = fmaf(e, c_hi[7 - k], d);
            }
            out2[rowbase + t] = a;
            g_cD[rowbase + t] = d;
        }
    }
}

// ======================================================================
// Kernel 3: flash attention fused with (attn @ cD), fp16 hi/lo 3-MMA.
// 512 threads / 16 warps: S 4Mx4N (warp 32x32), PV 8 row-groups x 2 col-
// groups x 5 frags. Same 128x128 tiles & SMEM; regs fit 128 -> 4 warps/SMSP.
// ======================================================================
#define SH68   68                 // b32 stride per row
#define QT_B32 (128*SH68)         // 8704 b32 per 128-row tile
#define FL_SMEM ((4*QT_B32 + 2*72*SH68 + 1024 + 384) * 4)   // 184064 B

__global__ __launch_bounds__(512, 1) void flash_f16_kernel(float* __restrict__ out1)
{
    extern __shared__ __align__(16) uint32_t smw[];
    uint32_t* Qhi  = smw;                   // [128][68]
    uint32_t* Qlo  = Qhi + QT_B32;
    uint32_t* Khi  = Qlo + QT_B32;          // aliased as Phi
    uint32_t* Klo  = Khi + QT_B32;          // aliased as Plo
    uint32_t* cDhi = Klo + QT_B32;          // [72][68]  (transposed: [w][keypair])
    uint32_t* cDlo = cDhi + 72*SH68;
    float* rmax = (float*)(cDlo + 72*SH68); // [128][4]
    float* rsum = rmax + 512;               // [128][4]
    float* m_s  = rsum + 512;               // [128]
    float* l_s  = m_s + 128;                // [128]
    float* al_s = l_s + 128;                // [128]

    const int tid  = threadIdx.x;
    const int lane = tid & 31;
    const int warp = tid >> 5;          // 0..15
    const int g    = lane >> 2;
    const int tig  = lane & 3;
    const int wm   = warp & 3;          // S: M group (32 rows)
    const int wn   = warp >> 2;         // S: N group (32 cols), 0..3
    const int r8   = warp & 7;          // PV: row group (16 rows)
    const int wn2  = warp >> 3;         // PV: col group, 0..1

    const int bh = blockIdx.y;
    const int q0 = blockIdx.x * 128;
    const float* Qg  = g_Q  + (size_t)bh * SEQ * DKD;
    const float* Kg  = g_K  + (size_t)bh * SEQ * DKD;
    const float* cDg = g_cD + (size_t)bh * SEQ * WAW;

    // ---- load + split Q (once) ----
#pragma unroll
    for (int u = 0; u < 8; u++) {
        const int idx = tid + 512*u;
        const int r = idx >> 5, c4 = idx & 31;
        const float4 q4 = *(const float4*)(Qg + (size_t)(q0 + r)*DKD + c4*4);
        uint32_t h0, l0, h1, l1;
        split_h2(q4.x, q4.y, h0, l0);
        split_h2(q4.z, q4.w, h1, l1);
        Qhi[r*SH68 + 2*c4]     = h0;  Qhi[r*SH68 + 2*c4 + 1] = h1;
        Qlo[r*SH68 + 2*c4]     = l0;  Qlo[r*SH68 + 2*c4 + 1] = l1;
    }
    for (int i = tid; i < 5*SH68; i += 512) {   // zero cD pad rows 67..71
        cDhi[67*SH68 + i] = 0;
        cDlo[67*SH68 + i] = 0;
    }
    if (tid < 128) { m_s[tid] = -1e30f; l_s[tid] = 0.0f; }

    float o[5][4];
#pragma unroll
    for (int f = 0; f < 5; f++)
#pragma unroll
        for (int q = 0; q < 4; q++) o[f][q] = 0.0f;

    __syncthreads();

    for (int kt = 0; kt < 16; kt++) {
        const int n0 = kt * 128;
        // ---- load + split K tile ----
#pragma unroll
        for (int u = 0; u < 8; u++) {
            const int idx = tid + 512*u;
            const int r = idx >> 5, c4 = idx & 31;
            const float4 k4 = *(const float4*)(Kg + (size_t)(n0 + r)*DKD + c4*4);
            uint32_t h0, l0, h1, l1;
            split_h2(k4.x, k4.y, h0, l0);
            split_h2(k4.z, k4.w, h1, l1);
            Khi[r*SH68 + 2*c4]     = h0;  Khi[r*SH68 + 2*c4 + 1] = h1;
            Klo[r*SH68 + 2*c4]     = l0;  Klo[r*SH68 + 2*c4 + 1] = l1;
        }
        // ---- load + split cD tile, transposed [w][keypair] ----
#pragma unroll
        for (int u = 0; u < 8; u++) {
            const int idx = tid + 512*u;
            const int j2 = idx >> 6, w = idx & 63;
            const float v0 = cDg[(size_t)(n0 + 2*j2    )*WAW + w];
            const float v1 = cDg[(size_t)(n0 + 2*j2 + 1)*WAW + w];
            uint32_t h, l;
            split_h2(v0, v1, h, l);
            cDhi[w*SH68 + j2] = h;
            cDlo[w*SH68 + j2] = l;
        }
        if (tid < 256) {   // tail: w = 64..66
            const int wt = tid & 3, j2 = tid >> 2;
            if (wt < 3) {
                const int w = 64 + wt;
                const float v0 = cDg[(size_t)(n0 + 2*j2    )*WAW + w];
                const float v1 = cDg[(size_t)(n0 + 2*j2 + 1)*WAW + w];
                uint32_t h, l;
                split_h2(v0, v1, h, l);
                cDhi[w*SH68 + j2] = h;
                cDlo[w*SH68 + j2] = l;
            }
        }
        __syncthreads();

        // ---- S = Q K^T : fp16 hi/lo 3-MMA, warp tile 32x32 ----
        float s[2][4][4];
#pragma unroll
        for (int mt = 0; mt < 2; mt++)
#pragma unroll
            for (int nt = 0; nt < 4; nt++)
#pragma unroll
                for (int q = 0; q < 4; q++) s[mt][nt][q] = 0.0f;

#pragma unroll 2
        for (int ks = 0; ks < 8; ks++) {
            const int k0b = ks * 8;
            uint32_t ah[2][4], al_[2][4];
#pragma unroll
            for (int mt = 0; mt < 2; mt++) {
                const int rb = wm*32 + mt*16 + g;
                ah[mt][0] = Qhi[(rb    )*SH68 + k0b + tig];
                ah[mt][1] = Qhi[(rb + 8)*SH68 + k0b + tig];
                ah[mt][2] = Qhi[(rb    )*SH68 + k0b + tig + 4];
                ah[mt][3] = Qhi[(rb + 8)*SH68 + k0b + tig + 4];
                al_[mt][0] = Qlo[(rb    )*SH68 + k0b + tig];
                al_[mt][1] = Qlo[(rb + 8)*SH68 + k0b + tig];
                al_[mt][2] = Qlo[(rb    )*SH68 + k0b + tig + 4];
                al_[mt][3] = Qlo[(rb + 8)*SH68 + k0b + tig + 4];
            }
#pragma unroll
            for (int nt = 0; nt < 4; nt++) {
                const int nb = wn*32 + nt*8 + g;
                const uint32_t bh0 = Khi[nb*SH68 + k0b + tig];
                const uint32_t bh1 = Khi[nb*SH68 + k0b + tig + 4];
                const uint32_t bl0 = Klo[nb*SH68 + k0b + tig];
                const uint32_t bl1 = Klo[nb*SH68 + k0b + tig + 4];
#pragma unroll
                for (int mt = 0; mt < 2; mt++) {
                    mma_f16(s[mt][nt][0], s[mt][nt][1], s[mt][nt][2], s[mt][nt][3],
                            ah[mt][0], ah[mt][1], ah[mt][2], ah[mt][3], bh0, bh1);
                    mma_f16(s[mt][nt][0], s[mt][nt][1], s[mt][nt][2], s[mt][nt][3],
                            ah[mt][0], ah[mt][1], ah[mt][2], ah[mt][3], bl0, bl1);
                    mma_f16(s[mt][nt][0], s[mt][nt][1], s[mt][nt][2], s[mt][nt][3],
                            al_[mt][0], al_[mt][1], al_[mt][2], al_[mt][3], bh0, bh1);
                }
            }
        }

        // ---- row max (quad shfl + 4-way cross-warp SMEM) ----
        float mx[2][2];
#pragma unroll
        for (int mt = 0; mt < 2; mt++)
#pragma unroll
            for (int hf = 0; hf < 2; hf++) {
                float m = -1e30f;
#pragma unroll
                for (int nt = 0; nt < 4; nt++)
                    m = fmaxf(m, fmaxf(s[mt][nt][2*hf], s[mt][nt][2*hf+1]));
                m = fmaxf(m, __shfl_xor_sync(0xffffffffu, m, 1));
                m = fmaxf(m, __shfl_xor_sync(0xffffffffu, m, 2));
                mx[mt][hf] = m;
            }
        if (tig == 0) {
#pragma unroll
            for (int mt = 0; mt < 2; mt++)
#pragma unroll
                for (int hf = 0; hf < 2; hf++) {
                    const int row = wm*32 + mt*16 + g + 8*hf;
                    rmax[row*4 + wn] = mx[mt][hf];
                }
        }
        __syncthreads();   // all K-fragment reads done -> P writes legal

        float mnew[2][2], alv[2][2], ssum[2][2];
#pragma unroll
        for (int mt = 0; mt < 2; mt++)
#pragma unroll
            for (int hf = 0; hf < 2; hf++) {
                const int row = wm*32 + mt*16 + g + 8*hf;
                const float tm = fmaxf(fmaxf(rmax[row*4], rmax[row*4+1]),
                                       fmaxf(rmax[row*4+2], rmax[row*4+3]));
                const float mo = m_s[row];
                const float mn = fmaxf(mo, tm);
                mnew[mt][hf] = mn;
                alv[mt][hf]  = __expf(mo - mn);
                ssum[mt][hf] = 0.0f;
            }
#pragma unroll
        for (int mt = 0; mt < 2; mt++) {
            const int r0 = wm*32 + mt*16 + g;
#pragma unroll
            for (int nt = 0; nt < 4; nt++) {
                const int cb = 16*wn + 4*nt + tig;     // b32 col 0..63
                float p0 = __expf(s[mt][nt][0] - mnew[mt][0]);
                float p1 = __expf(s[mt][nt][1] - mnew[mt][0]);
                float p2 = __expf(s[mt][nt][2] - mnew[mt][1]);
                float p3 = __expf(s[mt][nt][3] - mnew[mt][1]);
                ssum[mt][0] += p0 + p1;
                ssum[mt][1] += p2 + p3;
                uint32_t h, l;
                split_h2(p0, p1, h, l);
                Khi[(r0    )*SH68 + cb] = h;   // Phi
                Klo[(r0    )*SH68 + cb] = l;   // Plo
                split_h2(p2, p3, h, l);
                Khi[(r0 + 8)*SH68 + cb] = h;
                Klo[(r0 + 8)*SH68 + cb] = l;
            }
        }
#pragma unroll
        for (int mt = 0; mt < 2; mt++)
#pragma unroll
            for (int hf = 0; hf < 2; hf++) {
                float sv = ssum[mt][hf];
                sv += __shfl_xor_sync(0xffffffffu, sv, 1);
                sv += __shfl_xor_sync(0xffffffffu, sv, 2);
                if (tig == 0) {
                    const int row = wm*32 + mt*16 + g + 8*hf;
                    rsum[row*4 + wn] = sv;
                }
            }
        __syncthreads();

        if (wn == 0 && tig == 0) {
#pragma unroll
            for (int mt = 0; mt < 2; mt++)
#pragma unroll
                for (int hf = 0; hf < 2; hf++) {
                    const int row = wm*32 + mt*16 + g + 8*hf;
                    const float ts = (rsum[row*4] + rsum[row*4+1])
                                   + (rsum[row*4+2] + rsum[row*4+3]);
                    l_s[row]  = l_s[row]*alv[mt][hf] + ts;
                    m_s[row]  = mnew[mt][hf];
                    al_s[row] = alv[mt][hf];
                }
        }
        __syncthreads();

        // ---- PV: o += P @ cD^T, rows r8*16..+16, frags nt = wn2*4 + f ----
        {
            const int rb = r8*16 + g;
            const float a0 = al_s[rb], a1 = al_s[rb + 8];
#pragma unroll
            for (int f = 0; f < 5; f++) {
                o[f][0] *= a0; o[f][1] *= a0;
                o[f][2] *= a1; o[f][3] *= a1;
            }
#pragma unroll 2
            for (int ks = 0; ks < 8; ks++) {
                const int k0b = ks * 8;
                uint32_t ph[4], pl[4];
                ph[0] = Khi[(rb    )*SH68 + k0b + tig];
                ph[1] = Khi[(rb + 8)*SH68 + k0b + tig];
                ph[2] = Khi[(rb    )*SH68 + k0b + tig + 4];
                ph[3] = Khi[(rb + 8)*SH68 + k0b + tig + 4];
                pl[0] = Klo[(rb    )*SH68 + k0b + tig];
                pl[1] = Klo[(rb + 8)*SH68 + k0b + tig];
                pl[2] = Klo[(rb    )*SH68 + k0b + tig + 4];
                pl[3] = Klo[(rb + 8)*SH68 + k0b + tig + 4];
#pragma unroll
                for (int f = 0; f < 5; f++) {
                    const int wr = (wn2*4 + f)*8 + g;
                    const uint32_t ch0 = cDhi[wr*SH68 + k0b + tig];
                    const uint32_t ch1 = cDhi[wr*SH68 + k0b + tig + 4];
                    const uint32_t cl0 = cDlo[wr*SH68 + k0b + tig];
                    const uint32_t cl1 = cDlo[wr*SH68 + k0b + tig + 4];
                    mma_f16(o[f][0], o[f][1], o[f][2], o[f][3],
                            ph[0], ph[1], ph[2], ph[3], ch0, ch1);
                    mma_f16(o[f][0], o[f][1], o[f][2], o[f][3],
                            ph[0], ph[1], ph[2], ph[3], cl0, cl1);
                    mma_f16(o[f][0], o[f][1], o[f][2], o[f][3],
                            pl[0], pl[1], pl[2], pl[3], ch0, ch1);
                }
            }
        }
        __syncthreads();   // before next tile overwrites K(=P)/cD
    }

    // ---- epilogue: wn2==0 writes nt 0..4 (cols 0..39), wn2==1 nt 5..8 ----
    const int rb = r8*16 + g;
    const float inv0 = 1.0f / l_s[rb];
    const float inv1 = 1.0f / l_s[rb + 8];
    const int b = bh >> 3, h = bh & 7;
    const size_t base0 = (size_t)(b*2048 + q0 + rb) * 536 + h*67;
    const size_t base1 = base0 + (size_t)8 * 536;
#pragma unroll
    for (int f = 0; f < 5; f++) {
        if (wn2 == 1 && f == 0) continue;    // nt=4 duplicated across groups
        const int nt = wn2*4 + f;
        const int col = nt*8 + 2*tig;
        if (col < WAW) {
            out1[base0 + col] = o[f][0] * inv0;
            out1[base1 + col] = o[f][2] * inv1;
        }
        if (col + 1 < WAW) {
            out1[base0 + col + 1] = o[f][1] * inv0;
            out1[base1 + col + 1] = o[f][3] * inv1;
        }
    }
}

// ======================================================================
extern "C" void kernel_launch(void* const* d_in, const int* in_sizes, int n_in,
                              void* d_out, int out_size)
{
    (void)in_sizes; (void)n_in; (void)out_size;
    const float* x  = (const float*)d_in[0];
    const float* Wq = (const float*)d_in[1];
    const float* Wk = (const float*)d_in[2];
    const float* Wv = (const float*)d_in[3];
    float* out = (float*)d_out;

    cudaFuncSetAttribute(qkv_mma_kernel, cudaFuncAttributeMaxDynamicSharedMemorySize,
                         QKV_SMEM);
    qkv_mma_kernel<<<dim3(8, 64, 3), 256, QKV_SMEM>>>(x, Wq, Wk, Wv,
                                                      out + OUT1_ELEMS);

    cudaFuncSetAttribute(flash_f16_kernel, cudaFuncAttributeMaxDynamicSharedMemorySize,
                         FL_SMEM);
    flash_f16_kernel<<<dim3(16, 32), 512, FL_SMEM>>>(out);
}